// round 12
// baseline (speedup 1.0000x reference)
#include <cuda_runtime.h>
#include <cstdint>

#define D_MODEL 1024
#define NH      16
#define DK      64
#define BATCH   2
#define SEQ     2048
#define MTOK    (BATCH*SEQ)     // 4096
#define QKV_N   (3*D_MODEL)     // 3072

// Scratch (alloc-free rule: __device__ globals)
__device__ float g_qkv[(size_t)MTOK * QKV_N];   // [4096, 3072]
__device__ float g_att[(size_t)MTOK * D_MODEL]; // [4096, 1024]

// ---------------------------------------------------------------------------
// tf32 helpers (legacy mma.sync path — works on base sm_103 target)
// ---------------------------------------------------------------------------
__device__ __forceinline__ uint32_t f2tf32(float x) {
    uint32_t u;
    asm("cvt.rna.tf32.f32 %0, %1;" : "=r"(u) : "f"(x));
    return u;
}

__device__ __forceinline__ void mma_tf32_16x8x8(
    float* c, const uint32_t* a, const uint32_t* b)
{
    asm volatile(
        "mma.sync.aligned.m16n8k8.row.col.f32.tf32.tf32.f32 "
        "{%0,%1,%2,%3}, {%4,%5,%6,%7}, {%8,%9}, {%0,%1,%2,%3};"
        : "+f"(c[0]), "+f"(c[1]), "+f"(c[2]), "+f"(c[3])
        : "r"(a[0]), "r"(a[1]), "r"(a[2]), "r"(a[3]),
          "r"(b[0]), "r"(b[1]));
}

// ---------------------------------------------------------------------------
// tf32 mma.sync GEMM: C[M,N] = A[M,K] @ B[N,K]^T + bias[N]
// CTA 128x128, K-chunk 32, 128 threads = 4 warps, warp tile 64x64 (R5 shape),
// double-buffered smem with stage-before-compute overlap (R6 attn pattern):
// one __syncthreads per K-chunk.
// ---------------------------------------------------------------------------
#define GKT 32
#define SSTR 36
#define G_STAGE (2 * 128 * SSTR)                       // floats (As+Bs)
#define GEMM_SMEM (2 * G_STAGE * (int)sizeof(float))   // 73728 B

__global__ __launch_bounds__(128) void gemm_mma_tf32(
    const float* __restrict__ A, const float* __restrict__ Bm,
    const float* __restrict__ bias, float* __restrict__ C,
    int M, int N, int K)
{
    extern __shared__ float smem[];

    const int tid = threadIdx.x;
    const int w   = tid >> 5;
    const int l   = tid & 31;
    const int gid = l >> 2;
    const int t4  = l & 3;
    const int wm  = (w & 1) * 64;
    const int wn  = (w >> 1) * 64;
    const int row0 = blockIdx.y * 128;
    const int col0 = blockIdx.x * 128;

    float acc[4][8][4];
#pragma unroll
    for (int mi = 0; mi < 4; mi++)
#pragma unroll
        for (int ni = 0; ni < 8; ni++)
#pragma unroll
            for (int q = 0; q < 4; q++) acc[mi][ni][q] = 0.f;

    auto stage = [&](int it) {
        const int k0 = it * GKT;
        float* Ad = smem + (it & 1) * G_STAGE;
        float* Bd = Ad + 128 * SSTR;
#pragma unroll
        for (int j = 0; j < 8; j++) {
            int i  = tid + 128 * j;
            int r  = i >> 3;
            int c4 = (i & 7) * 4;
            float4 a = *(const float4*)(A  + (size_t)(row0 + r) * K + k0 + c4);
            float4 b = *(const float4*)(Bm + (size_t)(col0 + r) * K + k0 + c4);
            *(uint4*)&Ad[r * SSTR + c4] =
                make_uint4(f2tf32(a.x), f2tf32(a.y), f2tf32(a.z), f2tf32(a.w));
            *(uint4*)&Bd[r * SSTR + c4] =
                make_uint4(f2tf32(b.x), f2tf32(b.y), f2tf32(b.z), f2tf32(b.w));
        }
    };

    const int nK = K / GKT;
    stage(0);
    __syncthreads();

    for (int it = 0; it < nK; it++) {
        // Stage next chunk into the other buffer (last read 2 iters ago, synced)
        if (it + 1 < nK) stage(it + 1);

        const float* As = smem + (it & 1) * G_STAGE;
        const float* Bs = As + 128 * SSTR;
#pragma unroll
        for (int ks = 0; ks < 4; ks++) {
            const int k8 = ks * 8;
            uint32_t af[4][4];
#pragma unroll
            for (int mi = 0; mi < 4; mi++) {
                int m = wm + mi * 16 + gid;
                af[mi][0] = __float_as_uint(As[m * SSTR + k8 + t4]);
                af[mi][1] = __float_as_uint(As[(m + 8) * SSTR + k8 + t4]);
                af[mi][2] = __float_as_uint(As[m * SSTR + k8 + t4 + 4]);
                af[mi][3] = __float_as_uint(As[(m + 8) * SSTR + k8 + t4 + 4]);
            }
            uint32_t bf[8][2];
#pragma unroll
            for (int ni = 0; ni < 8; ni++) {
                int n = wn + ni * 8 + gid;
                bf[ni][0] = __float_as_uint(Bs[n * SSTR + k8 + t4]);
                bf[ni][1] = __float_as_uint(Bs[n * SSTR + k8 + t4 + 4]);
            }
#pragma unroll
            for (int mi = 0; mi < 4; mi++)
#pragma unroll
                for (int ni = 0; ni < 8; ni++)
                    mma_tf32_16x8x8(acc[mi][ni], af[mi], bf[ni]);
        }
        __syncthreads();
    }

#pragma unroll
    for (int mi = 0; mi < 4; mi++) {
        int m = row0 + wm + mi * 16 + gid;
#pragma unroll
        for (int ni = 0; ni < 8; ni++) {
            int n = col0 + wn + ni * 8 + 2 * t4;
            float b0 = bias[n], b1 = bias[n + 1];
            float2 v0 = make_float2(acc[mi][ni][0] + b0, acc[mi][ni][1] + b1);
            float2 v1 = make_float2(acc[mi][ni][2] + b0, acc[mi][ni][3] + b1);
            *(float2*)&C[(size_t)m * N + n] = v0;
            *(float2*)&C[(size_t)(m + 8) * N + n] = v1;
        }
    }
}

// ---------------------------------------------------------------------------
// Flash attention (R6 variant — measured ~190us): causal, tf32 mma.sync,
// double-buffered K/V via LDG->STS overlap, one sync per tile.
// CTA: 128 queries of one (b,h), 4 warps x 32-query warp tile; key tile 64.
// 1/sqrt(dk)=0.125 folded into Q at stage time (exact).
// ---------------------------------------------------------------------------
#define QSTR 68   // == 4 (mod 32): conflict-free A/B fragment LDS
#define KSTR 68
#define VSTR 72   // == 8 (mod 32): conflict-free V B-fragment LDS
#define KV_STAGE (64 * KSTR + 64 * VSTR)   // floats
#define FA_SMEM ((128 * QSTR + 2 * KV_STAGE) * (int)sizeof(float))  // 106496

__global__ __launch_bounds__(128) void flash_attn_mma(
    const float* __restrict__ qkv, float* __restrict__ att)
{
    extern __shared__ float sm[];
    float* Qs = sm;                       // [128][QSTR]

    const int qt  = blockIdx.x;           // 0..15
    const int h   = blockIdx.y;
    const int b   = blockIdx.z;
    const int tid = threadIdx.x;
    const int w   = tid >> 5;
    const int l   = tid & 31;
    const int gid = l >> 2;
    const int t4  = l & 3;
    const int q0  = qt * 128;
    const int wq  = w * 32;
    const int q0w = q0 + wq;

    const float* base = qkv + (size_t)b * SEQ * QKV_N + h * DK;

    // Stage Q tile 128x64, scaled by 0.125 (exact), tf32-rounded
#pragma unroll
    for (int j = 0; j < 16; j++) {
        int i  = tid + 128 * j;
        int r  = i >> 4;
        int c4 = (i & 15) * 4;
        float4 v = *(const float4*)(base + (size_t)(q0 + r) * QKV_N + c4);
        uint4 u = make_uint4(f2tf32(v.x * 0.125f), f2tf32(v.y * 0.125f),
                             f2tf32(v.z * 0.125f), f2tf32(v.w * 0.125f));
        *(uint4*)&Qs[r * QSTR + c4] = u;
    }

    // Prologue: stage K/V tile 0 into buffer 0
    {
        float* Ks = sm + 128 * QSTR;
        float* Vs = Ks + 64 * KSTR;
#pragma unroll
        for (int j = 0; j < 8; j++) {
            int i  = tid + 128 * j;
            int r  = i >> 4;
            int c4 = (i & 15) * 4;
            const float* rp = base + (size_t)r * QKV_N + c4;
            float4 kv = *(const float4*)(rp + D_MODEL);
            float4 vv = *(const float4*)(rp + 2 * D_MODEL);
            *(uint4*)&Ks[r * KSTR + c4] =
                make_uint4(f2tf32(kv.x), f2tf32(kv.y), f2tf32(kv.z), f2tf32(kv.w));
            *(uint4*)&Vs[r * VSTR + c4] =
                make_uint4(f2tf32(vv.x), f2tf32(vv.y), f2tf32(vv.z), f2tf32(vv.w));
        }
    }
    __syncthreads();

    float oacc[2][8][4];
    float m_i[2][2], l_i[2][2];
#pragma unroll
    for (int mi = 0; mi < 2; mi++) {
#pragma unroll
        for (int hf = 0; hf < 2; hf++) { m_i[mi][hf] = -1e30f; l_i[mi][hf] = 0.f; }
#pragma unroll
        for (int dj = 0; dj < 8; dj++)
#pragma unroll
            for (int q = 0; q < 4; q++) oacc[mi][dj][q] = 0.f;
    }

    const int src1 = (l & ~3) | (t4 >> 1);
    const int src2 = src1 + 2;
    const bool odd = (t4 & 1);

    const int ntiles = 2 * qt + 2;
    for (int kt = 0; kt < ntiles; kt++) {
        const int k0 = kt * 64;

        // Stage next K/V tile into the other buffer (readers synced out)
        if (kt + 1 < ntiles) {
            const int kn = (kt + 1) * 64;
            float* Ks = sm + 128 * QSTR + ((kt + 1) & 1) * KV_STAGE;
            float* Vs = Ks + 64 * KSTR;
#pragma unroll
            for (int j = 0; j < 8; j++) {
                int i  = tid + 128 * j;
                int r  = i >> 4;
                int c4 = (i & 15) * 4;
                const float* rp = base + (size_t)(kn + r) * QKV_N + c4;
                float4 kv = *(const float4*)(rp + D_MODEL);
                float4 vv = *(const float4*)(rp + 2 * D_MODEL);
                *(uint4*)&Ks[r * KSTR + c4] =
                    make_uint4(f2tf32(kv.x), f2tf32(kv.y), f2tf32(kv.z), f2tf32(kv.w));
                *(uint4*)&Vs[r * VSTR + c4] =
                    make_uint4(f2tf32(vv.x), f2tf32(vv.y), f2tf32(vv.z), f2tf32(vv.w));
            }
        }

        if (k0 <= q0w + 31) {   // warp-uniform: this warp has unmasked keys here
            const float* Ks = sm + 128 * QSTR + (kt & 1) * KV_STAGE;
            const float* Vs = Ks + 64 * KSTR;

            // ---- S = Q @ K^T (warp tile 32x64) ----
            float sacc[2][8][4];
#pragma unroll
            for (int mi = 0; mi < 2; mi++)
#pragma unroll
                for (int nj = 0; nj < 8; nj++)
#pragma unroll
                    for (int q = 0; q < 4; q++) sacc[mi][nj][q] = 0.f;

#pragma unroll
            for (int kc = 0; kc < 8; kc++) {
                const int k8 = kc * 8;
                uint32_t af[2][4];
#pragma unroll
                for (int mi = 0; mi < 2; mi++) {
                    int m = wq + mi * 16 + gid;
                    af[mi][0] = __float_as_uint(Qs[m * QSTR + k8 + t4]);
                    af[mi][1] = __float_as_uint(Qs[(m + 8) * QSTR + k8 + t4]);
                    af[mi][2] = __float_as_uint(Qs[m * QSTR + k8 + t4 + 4]);
                    af[mi][3] = __float_as_uint(Qs[(m + 8) * QSTR + k8 + t4 + 4]);
                }
#pragma unroll
                for (int nj = 0; nj < 8; nj++) {
                    uint32_t bf[2];
                    bf[0] = __float_as_uint(Ks[(nj * 8 + gid) * KSTR + k8 + t4]);
                    bf[1] = __float_as_uint(Ks[(nj * 8 + gid) * KSTR + k8 + t4 + 4]);
                    mma_tf32_16x8x8(sacc[0][nj], af[0], bf);
                    mma_tf32_16x8x8(sacc[1][nj], af[1], bf);
                }
            }

            // ---- online softmax (scale folded into Q) ----
            const bool domask = (k0 + 63 > q0w);
#pragma unroll
            for (int mi = 0; mi < 2; mi++) {
#pragma unroll
                for (int hf = 0; hf < 2; hf++) {
                    const int qrow = q0w + mi * 16 + hf * 8 + gid;
                    float mloc = -1e30f;
#pragma unroll
                    for (int nj = 0; nj < 8; nj++) {
#pragma unroll
                        for (int c = 0; c < 2; c++) {
                            float v = sacc[mi][nj][2 * hf + c];
                            if (domask && (k0 + nj * 8 + 2 * t4 + c > qrow)) v = -1e30f;
                            sacc[mi][nj][2 * hf + c] = v;
                            mloc = fmaxf(mloc, v);
                        }
                    }
                    mloc = fmaxf(mloc, __shfl_xor_sync(0xffffffffu, mloc, 1));
                    mloc = fmaxf(mloc, __shfl_xor_sync(0xffffffffu, mloc, 2));
                    float mnew = fmaxf(m_i[mi][hf], mloc);
                    float corr = __expf(m_i[mi][hf] - mnew);
                    float ls = 0.f;
#pragma unroll
                    for (int nj = 0; nj < 8; nj++) {
#pragma unroll
                        for (int c = 0; c < 2; c++) {
                            float p = __expf(sacc[mi][nj][2 * hf + c] - mnew);
                            sacc[mi][nj][2 * hf + c] = p;
                            ls += p;
                        }
                    }
                    ls += __shfl_xor_sync(0xffffffffu, ls, 1);
                    ls += __shfl_xor_sync(0xffffffffu, ls, 2);
                    l_i[mi][hf] = l_i[mi][hf] * corr + ls;
                    m_i[mi][hf] = mnew;
#pragma unroll
                    for (int dj = 0; dj < 8; dj++) {
                        oacc[mi][dj][2 * hf + 0] *= corr;
                        oacc[mi][dj][2 * hf + 1] *= corr;
                    }
                }
            }

            // ---- O += P @ V  (P: C-frag -> A-frag via quad shuffles) ----
#pragma unroll
            for (int kc = 0; kc < 8; kc++) {
                uint32_t pa[2][4];
#pragma unroll
                for (int mi = 0; mi < 2; mi++) {
                    float e0 = __shfl_sync(0xffffffffu, sacc[mi][kc][0], src1);
                    float e1 = __shfl_sync(0xffffffffu, sacc[mi][kc][1], src1);
                    float e2 = __shfl_sync(0xffffffffu, sacc[mi][kc][2], src1);
                    float e3 = __shfl_sync(0xffffffffu, sacc[mi][kc][3], src1);
                    float f0 = __shfl_sync(0xffffffffu, sacc[mi][kc][0], src2);
                    float f1 = __shfl_sync(0xffffffffu, sacc[mi][kc][1], src2);
                    float f2 = __shfl_sync(0xffffffffu, sacc[mi][kc][2], src2);
                    float f3 = __shfl_sync(0xffffffffu, sacc[mi][kc][3], src2);
                    pa[mi][0] = f2tf32(odd ? e1 : e0);
                    pa[mi][1] = f2tf32(odd ? e3 : e2);
                    pa[mi][2] = f2tf32(odd ? f1 : f0);
                    pa[mi][3] = f2tf32(odd ? f3 : f2);
                }
#pragma unroll
                for (int dj = 0; dj < 8; dj++) {
                    uint32_t vb[2];
                    vb[0] = __float_as_uint(Vs[(kc * 8 + t4) * VSTR + dj * 8 + gid]);
                    vb[1] = __float_as_uint(Vs[(kc * 8 + t4 + 4) * VSTR + dj * 8 + gid]);
                    mma_tf32_16x8x8(oacc[0][dj], pa[0], vb);
                    mma_tf32_16x8x8(oacc[1][dj], pa[1], vb);
                }
            }
        }
        __syncthreads();
    }

    // Finalize: divide by l and write [b*S+q][h*64+d]
#pragma unroll
    for (int mi = 0; mi < 2; mi++) {
#pragma unroll
        for (int hf = 0; hf < 2; hf++) {
            float inv = 1.f / l_i[mi][hf];
            size_t row = (size_t)(b * SEQ + q0w + mi * 16 + hf * 8 + gid) * D_MODEL
                       + h * DK;
#pragma unroll
            for (int dj = 0; dj < 8; dj++) {
                float2 v = make_float2(oacc[mi][dj][2 * hf + 0] * inv,
                                       oacc[mi][dj][2 * hf + 1] * inv);
                *(float2*)&att[row + dj * 8 + 2 * t4] = v;
            }
        }
    }
}

// ---------------------------------------------------------------------------
extern "C" void kernel_launch(void* const* d_in, const int* in_sizes, int n_in,
                              void* d_out, int out_size)
{
    const float* x       = (const float*)d_in[0];
    // d_in[1] = causal mask (int32) — structure is known causal; unused
    const float* w_qkv_w = (const float*)d_in[2];
    const float* w_qkv_b = (const float*)d_in[3];
    const float* w_o_w   = (const float*)d_in[4];
    const float* w_o_b   = (const float*)d_in[5];
    float* out = (float*)d_out;

    float *qkv, *att;
    cudaGetSymbolAddress((void**)&qkv, g_qkv);
    cudaGetSymbolAddress((void**)&att, g_att);

    cudaFuncSetAttribute(gemm_mma_tf32,
                         cudaFuncAttributeMaxDynamicSharedMemorySize, GEMM_SMEM);
    cudaFuncSetAttribute(flash_attn_mma,
                         cudaFuncAttributeMaxDynamicSharedMemorySize, FA_SMEM);

    // 1) QKV projection: [4096,1024] @ [3072,1024]^T -> [4096,3072]
    dim3 g1(QKV_N / 128, MTOK / 128);
    gemm_mma_tf32<<<g1, 128, GEMM_SMEM>>>(x, w_qkv_w, w_qkv_b, qkv, MTOK, QKV_N, D_MODEL);

    // 2) Causal flash attention (tensor cores) -> [4096,1024]
    dim3 g2(SEQ / 128, NH, BATCH);
    flash_attn_mma<<<g2, 128, FA_SMEM>>>(qkv, att);

    // 3) Output projection: [4096,1024] @ [1024,1024]^T -> [4096,1024]
    dim3 g3(D_MODEL / 128, MTOK / 128);
    gemm_mma_tf32<<<g3, 128, GEMM_SMEM>>>(att, w_o_w, w_o_b, out, MTOK, D_MODEL, D_MODEL);
}

// round 13
// speedup vs baseline: 1.1086x; 1.1086x over previous
#include <cuda_runtime.h>
#include <cstdint>

#define D_MODEL 1024
#define NH      16
#define DK      64
#define BATCH   2
#define SEQ     2048
#define MTOK    (BATCH*SEQ)     // 4096
#define QKV_N   (3*D_MODEL)     // 3072

// Scratch (alloc-free rule: __device__ globals)
__device__ float g_qkv[(size_t)MTOK * QKV_N];   // [4096, 3072]
__device__ float g_att[(size_t)MTOK * D_MODEL]; // [4096, 1024]

// ---------------------------------------------------------------------------
// tf32 helpers (legacy mma.sync path — works on base sm_103 target)
// ---------------------------------------------------------------------------
__device__ __forceinline__ uint32_t f2tf32(float x) {
    uint32_t u;
    asm("cvt.rna.tf32.f32 %0, %1;" : "=r"(u) : "f"(x));
    return u;
}

__device__ __forceinline__ void mma_tf32_16x8x8(
    float* c, const uint32_t* a, const uint32_t* b)
{
    asm volatile(
        "mma.sync.aligned.m16n8k8.row.col.f32.tf32.tf32.f32 "
        "{%0,%1,%2,%3}, {%4,%5,%6,%7}, {%8,%9}, {%0,%1,%2,%3};"
        : "+f"(c[0]), "+f"(c[1]), "+f"(c[2]), "+f"(c[3])
        : "r"(a[0]), "r"(a[1]), "r"(a[2]), "r"(a[3]),
          "r"(b[0]), "r"(b[1]));
}

// ---------------------------------------------------------------------------
// tf32 mma.sync GEMM: C[M,N] = A[M,K] @ B[N,K]^T + bias[N]
// CTA 128x128, 128 threads = 4 warps, warp tile 64x64 (proven R5 shape),
// K-chunk 64 (halves chunk-boundary latency exposure vs 32).
// Single buffer, static-style indexing, 2 syncs per chunk.
// ---------------------------------------------------------------------------
#define GKT 64
#define SSTR 68   // == 4 (mod 32): conflict-free fragment LDS (same as attn Q)
#define GEMM_SMEM (2 * 128 * SSTR * (int)sizeof(float))   // 69632 B

__global__ __launch_bounds__(128) void gemm_mma_tf32(
    const float* __restrict__ A, const float* __restrict__ Bm,
    const float* __restrict__ bias, float* __restrict__ C,
    int M, int N, int K)
{
    extern __shared__ float smem[];
    float* As = smem;                 // [128][SSTR]
    float* Bs = smem + 128 * SSTR;    // [128][SSTR]

    const int tid = threadIdx.x;
    const int w   = tid >> 5;
    const int l   = tid & 31;
    const int gid = l >> 2;
    const int t4  = l & 3;
    const int wm  = (w & 1) * 64;
    const int wn  = (w >> 1) * 64;
    const int row0 = blockIdx.y * 128;
    const int col0 = blockIdx.x * 128;

    float acc[4][8][4];
#pragma unroll
    for (int mi = 0; mi < 4; mi++)
#pragma unroll
        for (int ni = 0; ni < 8; ni++)
#pragma unroll
            for (int q = 0; q < 4; q++) acc[mi][ni][q] = 0.f;

    for (int k0 = 0; k0 < K; k0 += GKT) {
        // Stage A and B tiles (128 rows x 64 k), tf32 RNA-rounded
#pragma unroll
        for (int j = 0; j < 16; j++) {
            int i  = tid + 128 * j;
            int r  = i >> 4;             // row 0..127
            int c4 = (i & 15) * 4;       // col 0,4,...,60
            float4 a = *(const float4*)(A  + (size_t)(row0 + r) * K + k0 + c4);
            float4 b = *(const float4*)(Bm + (size_t)(col0 + r) * K + k0 + c4);
            *(uint4*)&As[r * SSTR + c4] =
                make_uint4(f2tf32(a.x), f2tf32(a.y), f2tf32(a.z), f2tf32(a.w));
            *(uint4*)&Bs[r * SSTR + c4] =
                make_uint4(f2tf32(b.x), f2tf32(b.y), f2tf32(b.z), f2tf32(b.w));
        }
        __syncthreads();

#pragma unroll
        for (int ks = 0; ks < 8; ks++) {
            const int k8 = ks * 8;
            uint32_t af[4][4];
#pragma unroll
            for (int mi = 0; mi < 4; mi++) {
                int m = wm + mi * 16 + gid;
                af[mi][0] = __float_as_uint(As[m * SSTR + k8 + t4]);
                af[mi][1] = __float_as_uint(As[(m + 8) * SSTR + k8 + t4]);
                af[mi][2] = __float_as_uint(As[m * SSTR + k8 + t4 + 4]);
                af[mi][3] = __float_as_uint(As[(m + 8) * SSTR + k8 + t4 + 4]);
            }
            uint32_t bf[8][2];
#pragma unroll
            for (int ni = 0; ni < 8; ni++) {
                int n = wn + ni * 8 + gid;
                bf[ni][0] = __float_as_uint(Bs[n * SSTR + k8 + t4]);
                bf[ni][1] = __float_as_uint(Bs[n * SSTR + k8 + t4 + 4]);
            }
#pragma unroll
            for (int mi = 0; mi < 4; mi++)
#pragma unroll
                for (int ni = 0; ni < 8; ni++)
                    mma_tf32_16x8x8(acc[mi][ni], af[mi], bf[ni]);
        }
        __syncthreads();
    }

#pragma unroll
    for (int mi = 0; mi < 4; mi++) {
        int m = row0 + wm + mi * 16 + gid;
#pragma unroll
        for (int ni = 0; ni < 8; ni++) {
            int n = col0 + wn + ni * 8 + 2 * t4;
            float b0 = bias[n], b1 = bias[n + 1];
            float2 v0 = make_float2(acc[mi][ni][0] + b0, acc[mi][ni][1] + b1);
            float2 v1 = make_float2(acc[mi][ni][2] + b0, acc[mi][ni][3] + b1);
            *(float2*)&C[(size_t)m * N + n] = v0;
            *(float2*)&C[(size_t)(m + 8) * N + n] = v1;
        }
    }
}

// ---------------------------------------------------------------------------
// Flash attention (R6/R8 variant — measured ~190us): causal, tf32 mma.sync,
// double-buffered K/V via LDG->STS overlap, one sync per tile.
// CTA: 128 queries of one (b,h), 4 warps x 32-query warp tile; key tile 64.
// 1/sqrt(dk)=0.125 folded into Q at stage time (exact).
// ---------------------------------------------------------------------------
#define QSTR 68   // == 4 (mod 32): conflict-free A/B fragment LDS
#define KSTR 68
#define VSTR 72   // == 8 (mod 32): conflict-free V B-fragment LDS
#define KV_STAGE (64 * KSTR + 64 * VSTR)   // floats
#define FA_SMEM ((128 * QSTR + 2 * KV_STAGE) * (int)sizeof(float))  // 106496

__global__ __launch_bounds__(128) void flash_attn_mma(
    const float* __restrict__ qkv, float* __restrict__ att)
{
    extern __shared__ float sm[];
    float* Qs = sm;                       // [128][QSTR]

    const int qt  = blockIdx.x;           // 0..15
    const int h   = blockIdx.y;
    const int b   = blockIdx.z;
    const int tid = threadIdx.x;
    const int w   = tid >> 5;
    const int l   = tid & 31;
    const int gid = l >> 2;
    const int t4  = l & 3;
    const int q0  = qt * 128;
    const int wq  = w * 32;
    const int q0w = q0 + wq;

    const float* base = qkv + (size_t)b * SEQ * QKV_N + h * DK;

    // Stage Q tile 128x64, scaled by 0.125 (exact), tf32-rounded
#pragma unroll
    for (int j = 0; j < 16; j++) {
        int i  = tid + 128 * j;
        int r  = i >> 4;
        int c4 = (i & 15) * 4;
        float4 v = *(const float4*)(base + (size_t)(q0 + r) * QKV_N + c4);
        uint4 u = make_uint4(f2tf32(v.x * 0.125f), f2tf32(v.y * 0.125f),
                             f2tf32(v.z * 0.125f), f2tf32(v.w * 0.125f));
        *(uint4*)&Qs[r * QSTR + c4] = u;
    }

    // Prologue: stage K/V tile 0 into buffer 0
    {
        float* Ks = sm + 128 * QSTR;
        float* Vs = Ks + 64 * KSTR;
#pragma unroll
        for (int j = 0; j < 8; j++) {
            int i  = tid + 128 * j;
            int r  = i >> 4;
            int c4 = (i & 15) * 4;
            const float* rp = base + (size_t)r * QKV_N + c4;
            float4 kv = *(const float4*)(rp + D_MODEL);
            float4 vv = *(const float4*)(rp + 2 * D_MODEL);
            *(uint4*)&Ks[r * KSTR + c4] =
                make_uint4(f2tf32(kv.x), f2tf32(kv.y), f2tf32(kv.z), f2tf32(kv.w));
            *(uint4*)&Vs[r * VSTR + c4] =
                make_uint4(f2tf32(vv.x), f2tf32(vv.y), f2tf32(vv.z), f2tf32(vv.w));
        }
    }
    __syncthreads();

    float oacc[2][8][4];
    float m_i[2][2], l_i[2][2];
#pragma unroll
    for (int mi = 0; mi < 2; mi++) {
#pragma unroll
        for (int hf = 0; hf < 2; hf++) { m_i[mi][hf] = -1e30f; l_i[mi][hf] = 0.f; }
#pragma unroll
        for (int dj = 0; dj < 8; dj++)
#pragma unroll
            for (int q = 0; q < 4; q++) oacc[mi][dj][q] = 0.f;
    }

    const int src1 = (l & ~3) | (t4 >> 1);
    const int src2 = src1 + 2;
    const bool odd = (t4 & 1);

    const int ntiles = 2 * qt + 2;
    for (int kt = 0; kt < ntiles; kt++) {
        const int k0 = kt * 64;

        // Stage next K/V tile into the other buffer (readers synced out)
        if (kt + 1 < ntiles) {
            const int kn = (kt + 1) * 64;
            float* Ks = sm + 128 * QSTR + ((kt + 1) & 1) * KV_STAGE;
            float* Vs = Ks + 64 * KSTR;
#pragma unroll
            for (int j = 0; j < 8; j++) {
                int i  = tid + 128 * j;
                int r  = i >> 4;
                int c4 = (i & 15) * 4;
                const float* rp = base + (size_t)(kn + r) * QKV_N + c4;
                float4 kv = *(const float4*)(rp + D_MODEL);
                float4 vv = *(const float4*)(rp + 2 * D_MODEL);
                *(uint4*)&Ks[r * KSTR + c4] =
                    make_uint4(f2tf32(kv.x), f2tf32(kv.y), f2tf32(kv.z), f2tf32(kv.w));
                *(uint4*)&Vs[r * VSTR + c4] =
                    make_uint4(f2tf32(vv.x), f2tf32(vv.y), f2tf32(vv.z), f2tf32(vv.w));
            }
        }

        if (k0 <= q0w + 31) {   // warp-uniform: this warp has unmasked keys here
            const float* Ks = sm + 128 * QSTR + (kt & 1) * KV_STAGE;
            const float* Vs = Ks + 64 * KSTR;

            // ---- S = Q @ K^T (warp tile 32x64) ----
            float sacc[2][8][4];
#pragma unroll
            for (int mi = 0; mi < 2; mi++)
#pragma unroll
                for (int nj = 0; nj < 8; nj++)
#pragma unroll
                    for (int q = 0; q < 4; q++) sacc[mi][nj][q] = 0.f;

#pragma unroll
            for (int kc = 0; kc < 8; kc++) {
                const int k8 = kc * 8;
                uint32_t af[2][4];
#pragma unroll
                for (int mi = 0; mi < 2; mi++) {
                    int m = wq + mi * 16 + gid;
                    af[mi][0] = __float_as_uint(Qs[m * QSTR + k8 + t4]);
                    af[mi][1] = __float_as_uint(Qs[(m + 8) * QSTR + k8 + t4]);
                    af[mi][2] = __float_as_uint(Qs[m * QSTR + k8 + t4 + 4]);
                    af[mi][3] = __float_as_uint(Qs[(m + 8) * QSTR + k8 + t4 + 4]);
                }
#pragma unroll
                for (int nj = 0; nj < 8; nj++) {
                    uint32_t bf[2];
                    bf[0] = __float_as_uint(Ks[(nj * 8 + gid) * KSTR + k8 + t4]);
                    bf[1] = __float_as_uint(Ks[(nj * 8 + gid) * KSTR + k8 + t4 + 4]);
                    mma_tf32_16x8x8(sacc[0][nj], af[0], bf);
                    mma_tf32_16x8x8(sacc[1][nj], af[1], bf);
                }
            }

            // ---- online softmax (scale folded into Q) ----
            const bool domask = (k0 + 63 > q0w);
#pragma unroll
            for (int mi = 0; mi < 2; mi++) {
#pragma unroll
                for (int hf = 0; hf < 2; hf++) {
                    const int qrow = q0w + mi * 16 + hf * 8 + gid;
                    float mloc = -1e30f;
#pragma unroll
                    for (int nj = 0; nj < 8; nj++) {
#pragma unroll
                        for (int c = 0; c < 2; c++) {
                            float v = sacc[mi][nj][2 * hf + c];
                            if (domask && (k0 + nj * 8 + 2 * t4 + c > qrow)) v = -1e30f;
                            sacc[mi][nj][2 * hf + c] = v;
                            mloc = fmaxf(mloc, v);
                        }
                    }
                    mloc = fmaxf(mloc, __shfl_xor_sync(0xffffffffu, mloc, 1));
                    mloc = fmaxf(mloc, __shfl_xor_sync(0xffffffffu, mloc, 2));
                    float mnew = fmaxf(m_i[mi][hf], mloc);
                    float corr = __expf(m_i[mi][hf] - mnew);
                    float ls = 0.f;
#pragma unroll
                    for (int nj = 0; nj < 8; nj++) {
#pragma unroll
                        for (int c = 0; c < 2; c++) {
                            float p = __expf(sacc[mi][nj][2 * hf + c] - mnew);
                            sacc[mi][nj][2 * hf + c] = p;
                            ls += p;
                        }
                    }
                    ls += __shfl_xor_sync(0xffffffffu, ls, 1);
                    ls += __shfl_xor_sync(0xffffffffu, ls, 2);
                    l_i[mi][hf] = l_i[mi][hf] * corr + ls;
                    m_i[mi][hf] = mnew;
#pragma unroll
                    for (int dj = 0; dj < 8; dj++) {
                        oacc[mi][dj][2 * hf + 0] *= corr;
                        oacc[mi][dj][2 * hf + 1] *= corr;
                    }
                }
            }

            // ---- O += P @ V  (P: C-frag -> A-frag via quad shuffles) ----
#pragma unroll
            for (int kc = 0; kc < 8; kc++) {
                uint32_t pa[2][4];
#pragma unroll
                for (int mi = 0; mi < 2; mi++) {
                    float e0 = __shfl_sync(0xffffffffu, sacc[mi][kc][0], src1);
                    float e1 = __shfl_sync(0xffffffffu, sacc[mi][kc][1], src1);
                    float e2 = __shfl_sync(0xffffffffu, sacc[mi][kc][2], src1);
                    float e3 = __shfl_sync(0xffffffffu, sacc[mi][kc][3], src1);
                    float f0 = __shfl_sync(0xffffffffu, sacc[mi][kc][0], src2);
                    float f1 = __shfl_sync(0xffffffffu, sacc[mi][kc][1], src2);
                    float f2 = __shfl_sync(0xffffffffu, sacc[mi][kc][2], src2);
                    float f3 = __shfl_sync(0xffffffffu, sacc[mi][kc][3], src2);
                    pa[mi][0] = f2tf32(odd ? e1 : e0);
                    pa[mi][1] = f2tf32(odd ? e3 : e2);
                    pa[mi][2] = f2tf32(odd ? f1 : f0);
                    pa[mi][3] = f2tf32(odd ? f3 : f2);
                }
#pragma unroll
                for (int dj = 0; dj < 8; dj++) {
                    uint32_t vb[2];
                    vb[0] = __float_as_uint(Vs[(kc * 8 + t4) * VSTR + dj * 8 + gid]);
                    vb[1] = __float_as_uint(Vs[(kc * 8 + t4 + 4) * VSTR + dj * 8 + gid]);
                    mma_tf32_16x8x8(oacc[0][dj], pa[0], vb);
                    mma_tf32_16x8x8(oacc[1][dj], pa[1], vb);
                }
            }
        }
        __syncthreads();
    }

    // Finalize: divide by l and write [b*S+q][h*64+d]
#pragma unroll
    for (int mi = 0; mi < 2; mi++) {
#pragma unroll
        for (int hf = 0; hf < 2; hf++) {
            float inv = 1.f / l_i[mi][hf];
            size_t row = (size_t)(b * SEQ + q0w + mi * 16 + hf * 8 + gid) * D_MODEL
                       + h * DK;
#pragma unroll
            for (int dj = 0; dj < 8; dj++) {
                float2 v = make_float2(oacc[mi][dj][2 * hf + 0] * inv,
                                       oacc[mi][dj][2 * hf + 1] * inv);
                *(float2*)&att[row + dj * 8 + 2 * t4] = v;
            }
        }
    }
}

// ---------------------------------------------------------------------------
extern "C" void kernel_launch(void* const* d_in, const int* in_sizes, int n_in,
                              void* d_out, int out_size)
{
    const float* x       = (const float*)d_in[0];
    // d_in[1] = causal mask (int32) — structure is known causal; unused
    const float* w_qkv_w = (const float*)d_in[2];
    const float* w_qkv_b = (const float*)d_in[3];
    const float* w_o_w   = (const float*)d_in[4];
    const float* w_o_b   = (const float*)d_in[5];
    float* out = (float*)d_out;

    float *qkv, *att;
    cudaGetSymbolAddress((void**)&qkv, g_qkv);
    cudaGetSymbolAddress((void**)&att, g_att);

    cudaFuncSetAttribute(gemm_mma_tf32,
                         cudaFuncAttributeMaxDynamicSharedMemorySize, GEMM_SMEM);
    cudaFuncSetAttribute(flash_attn_mma,
                         cudaFuncAttributeMaxDynamicSharedMemorySize, FA_SMEM);

    // 1) QKV projection: [4096,1024] @ [3072,1024]^T -> [4096,3072]
    dim3 g1(QKV_N / 128, MTOK / 128);
    gemm_mma_tf32<<<g1, 128, GEMM_SMEM>>>(x, w_qkv_w, w_qkv_b, qkv, MTOK, QKV_N, D_MODEL);

    // 2) Causal flash attention (tensor cores) -> [4096,1024]
    dim3 g2(SEQ / 128, NH, BATCH);
    flash_attn_mma<<<g2, 128, FA_SMEM>>>(qkv, att);

    // 3) Output projection: [4096,1024] @ [1024,1024]^T -> [4096,1024]
    dim3 g3(D_MODEL / 128, MTOK / 128);
    gemm_mma_tf32<<<g3, 128, GEMM_SMEM>>>(att, w_o_w, w_o_b, out, MTOK, D_MODEL, D_MODEL);
}

// round 14
// speedup vs baseline: 1.8928x; 1.7074x over previous
#include <cuda_runtime.h>
#include <cstdint>

#define D_MODEL 1024
#define NH      16
#define DK      64
#define BATCH   2
#define SEQ     2048
#define MTOK    (BATCH*SEQ)     // 4096
#define QKV_N   (3*D_MODEL)     // 3072
#define NQT     (SEQ/128)       // 16 query tiles

// Scratch (alloc-free rule: __device__ globals)
__device__ float g_qkv[(size_t)MTOK * QKV_N];   // [4096, 3072]
__device__ float g_att[(size_t)MTOK * D_MODEL]; // [4096, 1024]

// ---------------------------------------------------------------------------
// tf32 helpers (legacy mma.sync path — works on base sm_103 target)
// ---------------------------------------------------------------------------
__device__ __forceinline__ uint32_t f2tf32(float x) {
    uint32_t u;
    asm("cvt.rna.tf32.f32 %0, %1;" : "=r"(u) : "f"(x));
    return u;
}

__device__ __forceinline__ void mma_tf32_16x8x8(
    float* c, const uint32_t* a, const uint32_t* b)
{
    asm volatile(
        "mma.sync.aligned.m16n8k8.row.col.f32.tf32.tf32.f32 "
        "{%0,%1,%2,%3}, {%4,%5,%6,%7}, {%8,%9}, {%0,%1,%2,%3};"
        : "+f"(c[0]), "+f"(c[1]), "+f"(c[2]), "+f"(c[3])
        : "r"(a[0]), "r"(a[1]), "r"(a[2]), "r"(a[3]),
          "r"(b[0]), "r"(b[1]));
}

// ---------------------------------------------------------------------------
// tf32 mma.sync GEMM (R8/R5 exact — measured 177us QKV; static smem is
// load-bearing: dynamic-smem variants regressed to 352/307us):
// C[M,N] = A[M,K] @ B[N,K]^T + bias[N]
// CTA 128x128, K-chunk 32, 128 threads = 4 warps, warp tile 64x64.
// ---------------------------------------------------------------------------
#define GKT 32
#define SSTR 36

__global__ __launch_bounds__(128) void gemm_mma_tf32(
    const float* __restrict__ A, const float* __restrict__ Bm,
    const float* __restrict__ bias, float* __restrict__ C,
    int M, int N, int K)
{
    __shared__ float As[128 * SSTR];
    __shared__ float Bs[128 * SSTR];

    const int tid = threadIdx.x;
    const int w   = tid >> 5;
    const int l   = tid & 31;
    const int gid = l >> 2;
    const int t4  = l & 3;
    const int wm  = (w & 1) * 64;
    const int wn  = (w >> 1) * 64;
    const int row0 = blockIdx.y * 128;
    const int col0 = blockIdx.x * 128;

    float acc[4][8][4];
#pragma unroll
    for (int mi = 0; mi < 4; mi++)
#pragma unroll
        for (int ni = 0; ni < 8; ni++)
#pragma unroll
            for (int q = 0; q < 4; q++) acc[mi][ni][q] = 0.f;

    for (int k0 = 0; k0 < K; k0 += GKT) {
#pragma unroll
        for (int j = 0; j < 8; j++) {
            int i  = tid + 128 * j;
            int r  = i >> 3;
            int c4 = (i & 7) * 4;
            float4 a = *(const float4*)(A  + (size_t)(row0 + r) * K + k0 + c4);
            float4 b = *(const float4*)(Bm + (size_t)(col0 + r) * K + k0 + c4);
            uint4 au = make_uint4(f2tf32(a.x), f2tf32(a.y), f2tf32(a.z), f2tf32(a.w));
            uint4 bu = make_uint4(f2tf32(b.x), f2tf32(b.y), f2tf32(b.z), f2tf32(b.w));
            *(uint4*)&As[r * SSTR + c4] = au;
            *(uint4*)&Bs[r * SSTR + c4] = bu;
        }
        __syncthreads();

#pragma unroll
        for (int ks = 0; ks < 4; ks++) {
            const int k8 = ks * 8;
            uint32_t af[4][4];
#pragma unroll
            for (int mi = 0; mi < 4; mi++) {
                int m = wm + mi * 16 + gid;
                af[mi][0] = __float_as_uint(As[m * SSTR + k8 + t4]);
                af[mi][1] = __float_as_uint(As[(m + 8) * SSTR + k8 + t4]);
                af[mi][2] = __float_as_uint(As[m * SSTR + k8 + t4 + 4]);
                af[mi][3] = __float_as_uint(As[(m + 8) * SSTR + k8 + t4 + 4]);
            }
            uint32_t bf[8][2];
#pragma unroll
            for (int ni = 0; ni < 8; ni++) {
                int n = wn + ni * 8 + gid;
                bf[ni][0] = __float_as_uint(Bs[n * SSTR + k8 + t4]);
                bf[ni][1] = __float_as_uint(Bs[n * SSTR + k8 + t4 + 4]);
            }
#pragma unroll
            for (int mi = 0; mi < 4; mi++)
#pragma unroll
                for (int ni = 0; ni < 8; ni++)
                    mma_tf32_16x8x8(acc[mi][ni], af[mi], bf[ni]);
        }
        __syncthreads();
    }

#pragma unroll
    for (int mi = 0; mi < 4; mi++) {
        int m = row0 + wm + mi * 16 + gid;
#pragma unroll
        for (int ni = 0; ni < 8; ni++) {
            int n = col0 + wn + ni * 8 + 2 * t4;
            float b0 = bias[n], b1 = bias[n + 1];
            float2 v0 = make_float2(acc[mi][ni][0] + b0, acc[mi][ni][1] + b1);
            float2 v1 = make_float2(acc[mi][ni][2] + b0, acc[mi][ni][3] + b1);
            *(float2*)&C[(size_t)m * N + n] = v0;
            *(float2*)&C[(size_t)(m + 8) * N + n] = v1;
        }
    }
}

// ---------------------------------------------------------------------------
// Flash attention: causal, tf32 mma.sync, double-buffered K/V (R6 pattern),
// BALANCED CAUSAL SCHEDULING: CTA bx processes q-tiles {bx, NQT-1-bx} ->
// every CTA does exactly 36 key-tiles; grid (8,16,2)=256 CTAs = one wave.
// 1/sqrt(dk)=0.125 folded into Q at stage time (exact).
// ---------------------------------------------------------------------------
#define QSTR 68   // == 4 (mod 32): conflict-free A/B fragment LDS
#define KSTR 68
#define VSTR 72   // == 8 (mod 32): conflict-free V B-fragment LDS
#define KV_STAGE (64 * KSTR + 64 * VSTR)   // floats
#define FA_SMEM ((128 * QSTR + 2 * KV_STAGE) * (int)sizeof(float))  // 106496

__global__ __launch_bounds__(128) void flash_attn_mma(
    const float* __restrict__ qkv, float* __restrict__ att)
{
    extern __shared__ float sm[];
    float* Qs = sm;                       // [128][QSTR]

    const int bx  = blockIdx.x;           // 0..7
    const int h   = blockIdx.y;
    const int b   = blockIdx.z;
    const int tid = threadIdx.x;
    const int w   = tid >> 5;
    const int l   = tid & 31;
    const int gid = l >> 2;
    const int t4  = l & 3;
    const int wq  = w * 32;

    const float* base = qkv + (size_t)b * SEQ * QKV_N + h * DK;

    const int src1 = (l & ~3) | (t4 >> 1);
    const int src2 = src1 + 2;
    const bool odd = (t4 & 1);

#pragma unroll 1
    for (int ph = 0; ph < 2; ph++) {
        const int qt  = ph ? (NQT - 1 - bx) : bx;
        const int q0  = qt * 128;
        const int q0w = q0 + wq;

        // Stage Q tile 128x64, scaled by 0.125 (exact), tf32-rounded
#pragma unroll
        for (int j = 0; j < 16; j++) {
            int i  = tid + 128 * j;
            int r  = i >> 4;
            int c4 = (i & 15) * 4;
            float4 v = *(const float4*)(base + (size_t)(q0 + r) * QKV_N + c4);
            uint4 u = make_uint4(f2tf32(v.x * 0.125f), f2tf32(v.y * 0.125f),
                                 f2tf32(v.z * 0.125f), f2tf32(v.w * 0.125f));
            *(uint4*)&Qs[r * QSTR + c4] = u;
        }

        // Prologue: stage K/V tile 0 into buffer 0
        {
            float* Ks = sm + 128 * QSTR;
            float* Vs = Ks + 64 * KSTR;
#pragma unroll
            for (int j = 0; j < 8; j++) {
                int i  = tid + 128 * j;
                int r  = i >> 4;
                int c4 = (i & 15) * 4;
                const float* rp = base + (size_t)r * QKV_N + c4;
                float4 kv = *(const float4*)(rp + D_MODEL);
                float4 vv = *(const float4*)(rp + 2 * D_MODEL);
                *(uint4*)&Ks[r * KSTR + c4] =
                    make_uint4(f2tf32(kv.x), f2tf32(kv.y), f2tf32(kv.z), f2tf32(kv.w));
                *(uint4*)&Vs[r * VSTR + c4] =
                    make_uint4(f2tf32(vv.x), f2tf32(vv.y), f2tf32(vv.z), f2tf32(vv.w));
            }
        }
        __syncthreads();

        float oacc[2][8][4];
        float m_i[2][2], l_i[2][2];
#pragma unroll
        for (int mi = 0; mi < 2; mi++) {
#pragma unroll
            for (int hf = 0; hf < 2; hf++) { m_i[mi][hf] = -1e30f; l_i[mi][hf] = 0.f; }
#pragma unroll
            for (int dj = 0; dj < 8; dj++)
#pragma unroll
                for (int q = 0; q < 4; q++) oacc[mi][dj][q] = 0.f;
        }

        const int ntiles = 2 * qt + 2;
        for (int kt = 0; kt < ntiles; kt++) {
            const int k0 = kt * 64;

            // Stage next K/V tile into the other buffer (readers synced out)
            if (kt + 1 < ntiles) {
                const int kn = (kt + 1) * 64;
                float* Ks = sm + 128 * QSTR + ((kt + 1) & 1) * KV_STAGE;
                float* Vs = Ks + 64 * KSTR;
#pragma unroll
                for (int j = 0; j < 8; j++) {
                    int i  = tid + 128 * j;
                    int r  = i >> 4;
                    int c4 = (i & 15) * 4;
                    const float* rp = base + (size_t)(kn + r) * QKV_N + c4;
                    float4 kv = *(const float4*)(rp + D_MODEL);
                    float4 vv = *(const float4*)(rp + 2 * D_MODEL);
                    *(uint4*)&Ks[r * KSTR + c4] =
                        make_uint4(f2tf32(kv.x), f2tf32(kv.y), f2tf32(kv.z), f2tf32(kv.w));
                    *(uint4*)&Vs[r * VSTR + c4] =
                        make_uint4(f2tf32(vv.x), f2tf32(vv.y), f2tf32(vv.z), f2tf32(vv.w));
                }
            }

            if (k0 <= q0w + 31) {   // warp-uniform causal skip
                const float* Ks = sm + 128 * QSTR + (kt & 1) * KV_STAGE;
                const float* Vs = Ks + 64 * KSTR;

                // ---- S = Q @ K^T (warp tile 32x64) ----
                float sacc[2][8][4];
#pragma unroll
                for (int mi = 0; mi < 2; mi++)
#pragma unroll
                    for (int nj = 0; nj < 8; nj++)
#pragma unroll
                        for (int q = 0; q < 4; q++) sacc[mi][nj][q] = 0.f;

#pragma unroll
                for (int kc = 0; kc < 8; kc++) {
                    const int k8 = kc * 8;
                    uint32_t af[2][4];
#pragma unroll
                    for (int mi = 0; mi < 2; mi++) {
                        int m = wq + mi * 16 + gid;
                        af[mi][0] = __float_as_uint(Qs[m * QSTR + k8 + t4]);
                        af[mi][1] = __float_as_uint(Qs[(m + 8) * QSTR + k8 + t4]);
                        af[mi][2] = __float_as_uint(Qs[m * QSTR + k8 + t4 + 4]);
                        af[mi][3] = __float_as_uint(Qs[(m + 8) * QSTR + k8 + t4 + 4]);
                    }
#pragma unroll
                    for (int nj = 0; nj < 8; nj++) {
                        uint32_t bf[2];
                        bf[0] = __float_as_uint(Ks[(nj * 8 + gid) * KSTR + k8 + t4]);
                        bf[1] = __float_as_uint(Ks[(nj * 8 + gid) * KSTR + k8 + t4 + 4]);
                        mma_tf32_16x8x8(sacc[0][nj], af[0], bf);
                        mma_tf32_16x8x8(sacc[1][nj], af[1], bf);
                    }
                }

                // ---- online softmax (scale folded into Q) ----
                const bool domask = (k0 + 63 > q0w);
#pragma unroll
                for (int mi = 0; mi < 2; mi++) {
#pragma unroll
                    for (int hf = 0; hf < 2; hf++) {
                        const int qrow = q0w + mi * 16 + hf * 8 + gid;
                        float mloc = -1e30f;
#pragma unroll
                        for (int nj = 0; nj < 8; nj++) {
#pragma unroll
                            for (int c = 0; c < 2; c++) {
                                float v = sacc[mi][nj][2 * hf + c];
                                if (domask && (k0 + nj * 8 + 2 * t4 + c > qrow)) v = -1e30f;
                                sacc[mi][nj][2 * hf + c] = v;
                                mloc = fmaxf(mloc, v);
                            }
                        }
                        mloc = fmaxf(mloc, __shfl_xor_sync(0xffffffffu, mloc, 1));
                        mloc = fmaxf(mloc, __shfl_xor_sync(0xffffffffu, mloc, 2));
                        float mnew = fmaxf(m_i[mi][hf], mloc);
                        float corr = __expf(m_i[mi][hf] - mnew);
                        float ls = 0.f;
#pragma unroll
                        for (int nj = 0; nj < 8; nj++) {
#pragma unroll
                            for (int c = 0; c < 2; c++) {
                                float p = __expf(sacc[mi][nj][2 * hf + c] - mnew);
                                sacc[mi][nj][2 * hf + c] = p;
                                ls += p;
                            }
                        }
                        ls += __shfl_xor_sync(0xffffffffu, ls, 1);
                        ls += __shfl_xor_sync(0xffffffffu, ls, 2);
                        l_i[mi][hf] = l_i[mi][hf] * corr + ls;
                        m_i[mi][hf] = mnew;
#pragma unroll
                        for (int dj = 0; dj < 8; dj++) {
                            oacc[mi][dj][2 * hf + 0] *= corr;
                            oacc[mi][dj][2 * hf + 1] *= corr;
                        }
                    }
                }

                // ---- O += P @ V  (P: C-frag -> A-frag via quad shuffles) ----
#pragma unroll
                for (int kc = 0; kc < 8; kc++) {
                    uint32_t pa[2][4];
#pragma unroll
                    for (int mi = 0; mi < 2; mi++) {
                        float e0 = __shfl_sync(0xffffffffu, sacc[mi][kc][0], src1);
                        float e1 = __shfl_sync(0xffffffffu, sacc[mi][kc][1], src1);
                        float e2 = __shfl_sync(0xffffffffu, sacc[mi][kc][2], src1);
                        float e3 = __shfl_sync(0xffffffffu, sacc[mi][kc][3], src1);
                        float f0 = __shfl_sync(0xffffffffu, sacc[mi][kc][0], src2);
                        float f1 = __shfl_sync(0xffffffffu, sacc[mi][kc][1], src2);
                        float f2 = __shfl_sync(0xffffffffu, sacc[mi][kc][2], src2);
                        float f3 = __shfl_sync(0xffffffffu, sacc[mi][kc][3], src2);
                        pa[mi][0] = f2tf32(odd ? e1 : e0);
                        pa[mi][1] = f2tf32(odd ? e3 : e2);
                        pa[mi][2] = f2tf32(odd ? f1 : f0);
                        pa[mi][3] = f2tf32(odd ? f3 : f2);
                    }
#pragma unroll
                    for (int dj = 0; dj < 8; dj++) {
                        uint32_t vb[2];
                        vb[0] = __float_as_uint(Vs[(kc * 8 + t4) * VSTR + dj * 8 + gid]);
                        vb[1] = __float_as_uint(Vs[(kc * 8 + t4 + 4) * VSTR + dj * 8 + gid]);
                        mma_tf32_16x8x8(oacc[0][dj], pa[0], vb);
                        mma_tf32_16x8x8(oacc[1][dj], pa[1], vb);
                    }
                }
            }
            __syncthreads();
        }

        // Finalize: divide by l and write [b*S+q][h*64+d]
#pragma unroll
        for (int mi = 0; mi < 2; mi++) {
#pragma unroll
            for (int hf = 0; hf < 2; hf++) {
                float inv = 1.f / l_i[mi][hf];
                size_t row = (size_t)(b * SEQ + q0w + mi * 16 + hf * 8 + gid) * D_MODEL
                           + h * DK;
#pragma unroll
                for (int dj = 0; dj < 8; dj++) {
                    float2 v = make_float2(oacc[mi][dj][2 * hf + 0] * inv,
                                           oacc[mi][dj][2 * hf + 1] * inv);
                    *(float2*)&att[row + dj * 8 + 2 * t4] = v;
                }
            }
        }
        __syncthreads();   // isolate phases (Qs/KV restaged next iteration)
    }
}

// ---------------------------------------------------------------------------
extern "C" void kernel_launch(void* const* d_in, const int* in_sizes, int n_in,
                              void* d_out, int out_size)
{
    const float* x       = (const float*)d_in[0];
    // d_in[1] = causal mask (int32) — structure is known causal; unused
    const float* w_qkv_w = (const float*)d_in[2];
    const float* w_qkv_b = (const float*)d_in[3];
    const float* w_o_w   = (const float*)d_in[4];
    const float* w_o_b   = (const float*)d_in[5];
    float* out = (float*)d_out;

    float *qkv, *att;
    cudaGetSymbolAddress((void**)&qkv, g_qkv);
    cudaGetSymbolAddress((void**)&att, g_att);

    cudaFuncSetAttribute(flash_attn_mma,
                         cudaFuncAttributeMaxDynamicSharedMemorySize, FA_SMEM);

    // 1) QKV projection: [4096,1024] @ [3072,1024]^T -> [4096,3072]
    dim3 g1(QKV_N / 128, MTOK / 128);
    gemm_mma_tf32<<<g1, 128>>>(x, w_qkv_w, w_qkv_b, qkv, MTOK, QKV_N, D_MODEL);

    // 2) Causal flash attention, balanced pairing -> [4096,1024]
    dim3 g2(NQT / 2, NH, BATCH);
    flash_attn_mma<<<g2, 128, FA_SMEM>>>(qkv, att);

    // 3) Output projection: [4096,1024] @ [1024,1024]^T -> [4096,1024]
    dim3 g3(D_MODEL / 128, MTOK / 128);
    gemm_mma_tf32<<<g3, 128>>>(att, w_o_w, w_o_b, out, MTOK, D_MODEL, D_MODEL);
}